// round 1
// baseline (speedup 1.0000x reference)
#include <cuda_runtime.h>
#include <math.h>

#define NNODES 87381
#define NLEAF  65536

// ---------------- scratch (device globals; no allocation in kernel_launch) ---
__device__ float g_X[NNODES * 600];     // x-projections [ix|fx|ux|ox] per node
__device__ float g_C[NNODES * 150];     // cell states
__device__ float g_P[16384 * 450];      // per-level parent projections [ih|uh|oh]
__device__ float g_F[65536 * 150];      // per-level child f-projections (fh)
__device__ float g_Wx[300 * 600];       // packed [W_ix|W_fx|W_ux|W_ox]
__device__ float g_bx[600];
__device__ float g_Wh[150 * 600];       // packed [W_ih|W_uh|W_oh|W_fh]
__device__ float g_bh[600];             // packed [b_ih|b_uh|b_oh|b_fh]

__device__ __forceinline__ float sigf(float x) { return 1.0f / (1.0f + expf(-x)); }

// ---------------- weight packing ---------------------------------------------
__global__ void pack_kernel(
    const float* Wix, const float* bix, const float* Wfx, const float* bfx,
    const float* Wux, const float* bux, const float* Wox, const float* box_,
    const float* Wih, const float* bih, const float* Wfh, const float* bfh,
    const float* Wuh, const float* buh, const float* Woh, const float* boh)
{
    const int T0 = 300 * 600;           // Wx
    const int T1 = T0 + 150 * 600;      // Wh
    const int T2 = T1 + 600;            // bx
    const int T3 = T2 + 600;            // bh
    for (int idx = blockIdx.x * blockDim.x + threadIdx.x; idx < T3;
         idx += gridDim.x * blockDim.x) {
        if (idx < T0) {
            int r = idx / 600, c = idx % 600, m = c / 150, cc = c % 150;
            const float* W = (m == 0) ? Wix : (m == 1) ? Wfx : (m == 2) ? Wux : Wox;
            g_Wx[idx] = W[r * 150 + cc];
        } else if (idx < T1) {
            int t = idx - T0;
            int r = t / 600, c = t % 600, m = c / 150, cc = c % 150;
            const float* W = (m == 0) ? Wih : (m == 1) ? Wuh : (m == 2) ? Woh : Wfh;
            g_Wh[t] = W[r * 150 + cc];
        } else if (idx < T2) {
            int c = idx - T1, m = c / 150, cc = c % 150;
            const float* b = (m == 0) ? bix : (m == 1) ? bfx : (m == 2) ? bux : box_;
            g_bx[c] = b[cc];
        } else {
            int c = idx - T2, m = c / 150, cc = c % 150;
            const float* b = (m == 0) ? bih : (m == 1) ? buh : (m == 2) ? boh : bfh;
            g_bh[c] = b[cc];
        }
    }
}

// ---------------- generic fp32 GEMM: C[M x (gridDim.y*150)] = A[M x K] @ B ----
// BM=64, BN=150, BK=8, 240 threads, each thread 8x5 outputs.
// SUM4: logical A row p = sum of 4 physical rows 4p..4p+3 (child-sum fusion).
#define BM 64
#define BN 150
#define BK 8

template <bool SUM4>
__global__ __launch_bounds__(240) void sgemm_kernel(
    const float* __restrict__ A, const float* __restrict__ B,
    float* __restrict__ C, const float* __restrict__ bias,
    int M, int K, int ldc, int ldb)
{
    __shared__ float As[BK][BM];
    __shared__ float Bs[BK][BN];

    const int m0   = blockIdx.x * BM;
    const int col0 = blockIdx.y * BN;
    const int tid  = threadIdx.x;
    const int ty   = tid / 30;   // 0..7  -> 8 rows each
    const int tx   = tid % 30;   // 0..29 -> 5 cols each

    float acc[8][5];
#pragma unroll
    for (int i = 0; i < 8; i++)
#pragma unroll
        for (int j = 0; j < 5; j++) acc[i][j] = 0.0f;

    for (int k0 = 0; k0 < K; k0 += BK) {
        // A tile (transposed into smem)
        for (int i = tid; i < BM * BK; i += 240) {
            int kk = i % BK, mm = i / BK;
            int gm = m0 + mm, gk = k0 + kk;
            float v = 0.0f;
            if (gm < M && gk < K) {
                if (SUM4) {
                    const float* a = A + (size_t)(4 * gm) * K + gk;
                    v = a[0] + a[K] + a[2 * K] + a[3 * K];
                } else {
                    v = A[(size_t)gm * K + gk];
                }
            }
            As[kk][mm] = v;
        }
        // B tile (rows coalesced, BN=150 exact -> no col guard)
        for (int i = tid; i < BK * BN; i += 240) {
            int kk = i / BN, nn = i % BN;
            int gk = k0 + kk;
            Bs[kk][nn] = (gk < K) ? B[(size_t)gk * ldb + col0 + nn] : 0.0f;
        }
        __syncthreads();

#pragma unroll
        for (int kk = 0; kk < BK; kk++) {
            float a[8], b[5];
#pragma unroll
            for (int i = 0; i < 8; i++) a[i] = As[kk][ty * 8 + i];
#pragma unroll
            for (int j = 0; j < 5; j++) b[j] = Bs[kk][tx * 5 + j];
#pragma unroll
            for (int i = 0; i < 8; i++)
#pragma unroll
                for (int j = 0; j < 5; j++) acc[i][j] = fmaf(a[i], b[j], acc[i][j]);
        }
        __syncthreads();
    }

#pragma unroll
    for (int i = 0; i < 8; i++) {
        int gm = m0 + ty * 8 + i;
        if (gm < M) {
#pragma unroll
            for (int j = 0; j < 5; j++) {
                int gn = col0 + tx * 5 + j;
                float v = acc[i][j];
                if (bias) v += bias[gn];
                C[(size_t)gm * ldc + gn] = v;
            }
        }
    }
}

// ---------------- leaves: h_sum = 0, fc = 0 -----------------------------------
__global__ void leaf_kernel(float* __restrict__ out)
{
    int idx = blockIdx.x * blockDim.x + threadIdx.x;
    if (idx >= NLEAF * 150) return;
    int p = idx / 150, j = idx % 150;
    const float* Xr = g_X + (size_t)p * 600;
    float ig = sigf(Xr[j] + g_bh[j]);
    float ug = tanhf(Xr[300 + j] + g_bh[150 + j]);
    float og = sigf(Xr[450 + j] + g_bh[300 + j]);
    float c = ig * ug;
    g_C[(size_t)p * 150 + j] = c;
    out[(size_t)p * 150 + j] = og * tanhf(c);
}

// ---------------- internal level: gates + fc from P3/F ------------------------
__global__ void level_kernel(float* __restrict__ out, int off_p, int off_c, int n)
{
    int idx = blockIdx.x * blockDim.x + threadIdx.x;
    if (idx >= n * 150) return;
    int p = idx / 150, j = idx % 150;
    int g = off_p + p;
    const float* Xr = g_X + (size_t)g * 600;
    const float* Pr = g_P + (size_t)p * 450;

    float ig = sigf(Xr[j] + Pr[j] + g_bh[j]);
    float ug = tanhf(Xr[300 + j] + Pr[150 + j] + g_bh[150 + j]);
    float og = sigf(Xr[450 + j] + Pr[300 + j] + g_bh[300 + j]);
    float xf = Xr[150 + j] + g_bh[450 + j];

    float fc = 0.0f;
#pragma unroll
    for (int k = 0; k < 4; k++) {
        int cl = 4 * p + k;
        float f = sigf(xf + g_F[(size_t)cl * 150 + j]);
        fc = fmaf(f, g_C[(size_t)(off_c + cl) * 150 + j], fc);
    }
    float c = fmaf(ig, ug, fc);
    g_C[(size_t)g * 150 + j] = c;
    out[(size_t)g * 150 + j] = og * tanhf(c);
}

// ---------------- host orchestration ------------------------------------------
extern "C" void kernel_launch(void* const* d_in, const int* in_sizes, int n_in,
                              void* d_out, int out_size)
{
    const float* embs = (const float*)d_in[0];
    const float* Wix = (const float*)d_in[1];  const float* bix = (const float*)d_in[2];
    const float* Wfx = (const float*)d_in[3];  const float* bfx = (const float*)d_in[4];
    const float* Wux = (const float*)d_in[5];  const float* bux = (const float*)d_in[6];
    const float* Wox = (const float*)d_in[7];  const float* box_ = (const float*)d_in[8];
    const float* Wih = (const float*)d_in[9];  const float* bih = (const float*)d_in[10];
    const float* Wfh = (const float*)d_in[11]; const float* bfh = (const float*)d_in[12];
    const float* Wuh = (const float*)d_in[13]; const float* buh = (const float*)d_in[14];
    const float* Woh = (const float*)d_in[15]; const float* boh = (const float*)d_in[16];
    float* out = (float*)d_out;

    float *pX, *pWx, *pbx, *pWh, *pP, *pF;
    cudaGetSymbolAddress((void**)&pX,  g_X);
    cudaGetSymbolAddress((void**)&pWx, g_Wx);
    cudaGetSymbolAddress((void**)&pbx, g_bx);
    cudaGetSymbolAddress((void**)&pWh, g_Wh);
    cudaGetSymbolAddress((void**)&pP,  g_P);
    cudaGetSymbolAddress((void**)&pF,  g_F);

    static const int SIZES[9] = {65536, 16384, 4096, 1024, 256, 64, 16, 4, 1};
    static const int OFF[9]   = {0, 65536, 81920, 86016, 87040, 87296, 87360, 87376, 87380};

    // 1. pack weights
    pack_kernel<<<256, 256>>>(Wix, bix, Wfx, bfx, Wux, bux, Wox, box_,
                              Wih, bih, Wfh, bfh, Wuh, buh, Woh, boh);

    // 2. all x-projections: X = embs @ [Wix|Wfx|Wux|Wox] + b   (N x 600)
    {
        dim3 grid((NNODES + BM - 1) / BM, 4);
        sgemm_kernel<false><<<grid, 240>>>(embs, pWx, pX, pbx, NNODES, 300, 600, 600);
    }

    // 3. leaves
    leaf_kernel<<<(NLEAF * 150 + 255) / 256, 256>>>(out);

    // 4. internal levels, bottom-up
    for (int d = 1; d < 9; d++) {
        int n  = SIZES[d];
        int np = SIZES[d - 1];
        const float* hprev = out + (size_t)OFF[d - 1] * 150;

        // P3 = (sum of 4 children h) @ [W_ih|W_uh|W_oh]   (n x 450)
        {
            dim3 grid((n + BM - 1) / BM, 3);
            sgemm_kernel<true><<<grid, 240>>>(hprev, pWh, pP, nullptr, n, 150, 450, 600);
        }
        // F = h_children @ W_fh   (4n x 150)
        {
            dim3 grid((np + BM - 1) / BM, 1);
            sgemm_kernel<false><<<grid, 240>>>(hprev, pWh + 450, pF, nullptr, np, 150, 150, 600);
        }
        // gates / cell / h
        level_kernel<<<(n * 150 + 255) / 256, 256>>>(out, OFF[d], OFF[d - 1], n);
    }
}

// round 2
// speedup vs baseline: 2.6962x; 2.6962x over previous
#include <cuda_runtime.h>
#include <math.h>

#define NNODES 87381
#define NLEAF  65536

// ---------------- scratch (device globals; no allocation anywhere) -----------
// gate blocks padded 150 -> 160 throughout
__device__ float g_X[87424 * 640];   // x-projections [ix|fx|ux|ox], stride 640
__device__ float g_H[87424 * 160];   // padded h (mirror of out), stride 160
__device__ float g_C[NNODES * 150];  // cell states (compact)
__device__ float g_P[16384 * 480];   // parent projections [ih|uh|oh], stride 480
__device__ float g_F[65536 * 160];   // child f-projections, stride 160
__device__ float g_Wx[304 * 640];    // packed [W_ix|W_fx|W_ux|W_ox], K padded 300->304
__device__ float g_Wh[160 * 640];    // packed [W_ih|W_uh|W_oh|W_fh], K padded 150->160
__device__ float g_bx[640];          // [b_ix|b_fx|b_ux|b_ox]
__device__ float g_bh[640];          // [b_ih|b_uh|b_oh|b_fh]

__device__ __forceinline__ float sigf(float x) { return 1.0f / (1.0f + expf(-x)); }

__device__ __forceinline__ float to_tf32(float x) {
    unsigned u;
    asm("cvt.rna.tf32.f32 %0, %1;" : "=r"(u) : "f"(x));
    return __uint_as_float(u);
}

__device__ __forceinline__ void mma8(float* d, const unsigned* a, const unsigned* b) {
    asm volatile(
        "mma.sync.aligned.m16n8k8.row.col.f32.tf32.tf32.f32 "
        "{%0,%1,%2,%3}, {%4,%5,%6,%7}, {%8,%9}, {%0,%1,%2,%3};\n"
        : "+f"(d[0]), "+f"(d[1]), "+f"(d[2]), "+f"(d[3])
        : "r"(a[0]), "r"(a[1]), "r"(a[2]), "r"(a[3]), "r"(b[0]), "r"(b[1]));
}

// ---------------- weight packing ---------------------------------------------
__global__ void pack_kernel(
    const float* Wix, const float* bix, const float* Wfx, const float* bfx,
    const float* Wux, const float* bux, const float* Wox, const float* box_,
    const float* Wih, const float* bih, const float* Wfh, const float* bfh,
    const float* Wuh, const float* buh, const float* Woh, const float* boh)
{
    const int T0 = 304 * 640;            // Wx
    const int T1 = T0 + 160 * 640;       // Wh
    const int T2 = T1 + 640;             // bx
    const int T3 = T2 + 640;             // bh
    for (int idx = blockIdx.x * blockDim.x + threadIdx.x; idx < T3;
         idx += gridDim.x * blockDim.x) {
        if (idx < T0) {
            int r = idx / 640, c = idx % 640, m = c / 160, cc = c % 160;
            float v = 0.0f;
            if (r < 300 && cc < 150) {
                const float* W = (m == 0) ? Wix : (m == 1) ? Wfx : (m == 2) ? Wux : Wox;
                v = W[r * 150 + cc];
            }
            g_Wx[idx] = v;
        } else if (idx < T1) {
            int t = idx - T0;
            int r = t / 640, c = t % 640, m = c / 160, cc = c % 160;
            float v = 0.0f;
            if (r < 150 && cc < 150) {
                const float* W = (m == 0) ? Wih : (m == 1) ? Wuh : (m == 2) ? Woh : Wfh;
                v = W[r * 150 + cc];
            }
            g_Wh[t] = v;
        } else if (idx < T2) {
            int c = idx - T1, m = c / 160, cc = c % 160;
            float v = 0.0f;
            if (cc < 150) {
                const float* b = (m == 0) ? bix : (m == 1) ? bfx : (m == 2) ? bux : box_;
                v = b[cc];
            }
            g_bx[c] = v;
        } else {
            int c = idx - T2, m = c / 160, cc = c % 160;
            float v = 0.0f;
            if (cc < 150) {
                const float* b = (m == 0) ? bih : (m == 1) ? buh : (m == 2) ? boh : bfh;
                v = b[cc];
            }
            g_bh[c] = v;
        }
    }
}

// ---------------- tf32 tensor-core GEMM --------------------------------------
// C[M x (gridDim.y*160)] = A[M x Kreal] @ B (+bias). Tiles: BM=128, BN=160,
// BK=16. 512 threads = 16 warps as 4x4; warp tile 32x40 (2 m-frags x 5 n-frags
// of m16n8k8). SUM4: logical A row p = sum of physical rows 4p..4p+3.
// Smem strides 20 / 168 -> conflict-free fragment loads.
template<bool SUM4, bool BIAS>
__global__ __launch_bounds__(512, 1)
void mma_gemm(const float* __restrict__ A, int lda,
              const float* __restrict__ B, int ldb,
              float* __restrict__ C, int ldc,
              const float* __restrict__ bias,
              int M, int Kreal, int Kpad)
{
    __shared__ float As[128][20];
    __shared__ float Bs[16][168];

    const int tid    = threadIdx.x;
    const int lane   = tid & 31;
    const int wid    = tid >> 5;
    const int m_warp = (wid >> 2) * 32;
    const int n_warp = (wid & 3) * 40;
    const int m0     = blockIdx.x * 128;
    const int colblk = blockIdx.y * 160;

    float acc[2][5][4];
#pragma unroll
    for (int i = 0; i < 2; i++)
#pragma unroll
        for (int j = 0; j < 5; j++)
#pragma unroll
            for (int q = 0; q < 4; q++) acc[i][j][q] = 0.0f;

    float ra[4], rb[5];

    // --- prefetch helpers ---
    auto loadA = [&](int k0) {
#pragma unroll
        for (int e = 0; e < 4; e++) {
            int idx = tid + e * 512;
            int r = idx >> 4, c = idx & 15;
            int gm = m0 + r, gk = k0 + c;
            float v = 0.0f;
            if (gm < M && gk < Kreal) {
                if (SUM4) {
                    const float* ap = A + (size_t)(4 * gm) * lda + gk;
                    v = ap[0] + ap[lda] + ap[2 * (size_t)lda] + ap[3 * (size_t)lda];
                } else {
                    v = A[(size_t)gm * lda + gk];
                }
            }
            ra[e] = to_tf32(v);
        }
    };
    auto loadB = [&](int k0) {
#pragma unroll
        for (int e = 0; e < 5; e++) {
            int idx = tid + e * 512;
            int r = idx / 160, c = idx - r * 160;
            rb[e] = to_tf32(B[(size_t)(k0 + r) * ldb + colblk + c]);
        }
    };

    loadA(0);
    loadB(0);

    for (int k0 = 0; k0 < Kpad; k0 += 16) {
        // store prefetched tile to smem
#pragma unroll
        for (int e = 0; e < 4; e++) {
            int idx = tid + e * 512;
            As[idx >> 4][idx & 15] = ra[e];
        }
#pragma unroll
        for (int e = 0; e < 5; e++) {
            int idx = tid + e * 512;
            int r = idx / 160, c = idx - r * 160;
            Bs[r][c] = rb[e];
        }
        __syncthreads();

        if (k0 + 16 < Kpad) { loadA(k0 + 16); loadB(k0 + 16); }

        // compute two k8 sub-steps
#pragma unroll
        for (int ks = 0; ks < 2; ks++) {
            const int kk = ks * 8;
            unsigned a[2][4], b[5][2];
            const int rA = m_warp + (lane >> 2);
            const int cA = kk + (lane & 3);
#pragma unroll
            for (int i = 0; i < 2; i++) {
                a[i][0] = __float_as_uint(As[rA + 16 * i][cA]);
                a[i][1] = __float_as_uint(As[rA + 16 * i + 8][cA]);
                a[i][2] = __float_as_uint(As[rA + 16 * i][cA + 4]);
                a[i][3] = __float_as_uint(As[rA + 16 * i + 8][cA + 4]);
            }
            const int rB = kk + (lane & 3);
            const int cB = n_warp + (lane >> 2);
#pragma unroll
            for (int j = 0; j < 5; j++) {
                b[j][0] = __float_as_uint(Bs[rB][cB + 8 * j]);
                b[j][1] = __float_as_uint(Bs[rB + 4][cB + 8 * j]);
            }
#pragma unroll
            for (int i = 0; i < 2; i++)
#pragma unroll
                for (int j = 0; j < 5; j++) mma8(acc[i][j], a[i], b[j]);
        }
        __syncthreads();
    }

    // --- epilogue ---
    const int r0 = m0 + m_warp + (lane >> 2);
    const int c0 = colblk + n_warp + (lane & 3) * 2;
#pragma unroll
    for (int i = 0; i < 2; i++) {
        int r = r0 + 16 * i;
#pragma unroll
        for (int j = 0; j < 5; j++) {
            int c = c0 + 8 * j;
            float b0 = 0.0f, b1 = 0.0f;
            if (BIAS) { b0 = bias[c]; b1 = bias[c + 1]; }
            if (r < M) {
                C[(size_t)r * ldc + c]     = acc[i][j][0] + b0;
                C[(size_t)r * ldc + c + 1] = acc[i][j][1] + b1;
            }
            if (r + 8 < M) {
                C[(size_t)(r + 8) * ldc + c]     = acc[i][j][2] + b0;
                C[(size_t)(r + 8) * ldc + c + 1] = acc[i][j][3] + b1;
            }
        }
    }
}

// ---------------- leaves: h_sum = 0, fc = 0 -----------------------------------
__global__ void leaf_kernel(float* __restrict__ out)
{
    int idx = blockIdx.x * blockDim.x + threadIdx.x;
    if (idx >= NLEAF * 160) return;
    int p = idx / 160, j = idx - p * 160;
    if (j >= 150) { g_H[(size_t)p * 160 + j] = 0.0f; return; }
    const float* Xr = g_X + (size_t)p * 640;
    float ig = sigf(Xr[j] + g_bh[j]);
    float ug = tanhf(Xr[320 + j] + g_bh[160 + j]);
    float og = sigf(Xr[480 + j] + g_bh[320 + j]);
    float c = ig * ug;
    g_C[(size_t)p * 150 + j] = c;
    float h = og * tanhf(c);
    out[(size_t)p * 150 + j] = h;
    g_H[(size_t)p * 160 + j] = h;
}

// ---------------- internal level: gates + fc ----------------------------------
__global__ void level_kernel(float* __restrict__ out, int off_p, int off_c, int n)
{
    int idx = blockIdx.x * blockDim.x + threadIdx.x;
    if (idx >= n * 160) return;
    int p = idx / 160, j = idx - p * 160;
    int g = off_p + p;
    if (j >= 150) { g_H[(size_t)g * 160 + j] = 0.0f; return; }
    const float* Xr = g_X + (size_t)g * 640;
    const float* Pr = g_P + (size_t)p * 480;

    float ig = sigf(Xr[j]       + Pr[j]       + g_bh[j]);
    float ug = tanhf(Xr[320 + j] + Pr[160 + j] + g_bh[160 + j]);
    float og = sigf(Xr[480 + j] + Pr[320 + j] + g_bh[320 + j]);
    float xf = Xr[160 + j] + g_bh[480 + j];

    float fc = 0.0f;
#pragma unroll
    for (int k = 0; k < 4; k++) {
        int cl = 4 * p + k;
        float f = sigf(xf + g_F[(size_t)cl * 160 + j]);
        fc = fmaf(f, g_C[(size_t)(off_c + cl) * 150 + j], fc);
    }
    float c = fmaf(ig, ug, fc);
    g_C[(size_t)g * 150 + j] = c;
    float h = og * tanhf(c);
    out[(size_t)g * 150 + j] = h;
    g_H[(size_t)g * 160 + j] = h;
}

// ---------------- host orchestration ------------------------------------------
extern "C" void kernel_launch(void* const* d_in, const int* in_sizes, int n_in,
                              void* d_out, int out_size)
{
    const float* embs = (const float*)d_in[0];
    const float* Wix = (const float*)d_in[1];  const float* bix = (const float*)d_in[2];
    const float* Wfx = (const float*)d_in[3];  const float* bfx = (const float*)d_in[4];
    const float* Wux = (const float*)d_in[5];  const float* bux = (const float*)d_in[6];
    const float* Wox = (const float*)d_in[7];  const float* box_ = (const float*)d_in[8];
    const float* Wih = (const float*)d_in[9];  const float* bih = (const float*)d_in[10];
    const float* Wfh = (const float*)d_in[11]; const float* bfh = (const float*)d_in[12];
    const float* Wuh = (const float*)d_in[13]; const float* buh = (const float*)d_in[14];
    const float* Woh = (const float*)d_in[15]; const float* boh = (const float*)d_in[16];
    float* out = (float*)d_out;

    float *pX, *pH, *pWx, *pbx, *pWh, *pP, *pF;
    cudaGetSymbolAddress((void**)&pX,  g_X);
    cudaGetSymbolAddress((void**)&pH,  g_H);
    cudaGetSymbolAddress((void**)&pWx, g_Wx);
    cudaGetSymbolAddress((void**)&pbx, g_bx);
    cudaGetSymbolAddress((void**)&pWh, g_Wh);
    cudaGetSymbolAddress((void**)&pP,  g_P);
    cudaGetSymbolAddress((void**)&pF,  g_F);

    static const int SIZES[9] = {65536, 16384, 4096, 1024, 256, 64, 16, 4, 1};
    static const int OFF[9]   = {0, 65536, 81920, 86016, 87040, 87296, 87360, 87376, 87380};

    // 1. pack + pad weights/biases
    pack_kernel<<<512, 256>>>(Wix, bix, Wfx, bfx, Wux, bux, Wox, box_,
                              Wih, bih, Wfh, bfh, Wuh, buh, Woh, boh);

    // 2. X = embs @ [Wix|Wfx|Wux|Wox] + b   (N x 640, tf32 tensor cores)
    {
        dim3 grid((NNODES + 127) / 128, 4);
        mma_gemm<false, true><<<grid, 512>>>(embs, 300, pWx, 640, pX, 640, pbx,
                                             NNODES, 300, 304);
    }

    // 3. leaves
    leaf_kernel<<<(NLEAF * 160 + 255) / 256, 256>>>(out);

    // 4. internal levels, bottom-up
    for (int d = 1; d < 9; d++) {
        int n  = SIZES[d];
        int np = SIZES[d - 1];
        const float* hprev = pH + (size_t)OFF[d - 1] * 160;

        // P = (sum of 4 children h) @ [W_ih|W_uh|W_oh]   (n x 480)
        {
            dim3 grid((n + 127) / 128, 3);
            mma_gemm<true, false><<<grid, 512>>>(hprev, 160, pWh, 640, pP, 480,
                                                 nullptr, n, 160, 160);
        }
        // F = h_children @ W_fh   (np x 160)
        {
            dim3 grid((np + 127) / 128, 1);
            mma_gemm<false, false><<<grid, 512>>>(hprev, 160, pWh + 480, 640, pF, 160,
                                                  nullptr, np, 160, 160);
        }
        // gates / cell / h
        level_kernel<<<(n * 160 + 255) / 256, 256>>>(out, OFF[d], OFF[d - 1], n);
    }
}

// round 4
// speedup vs baseline: 4.1912x; 1.5545x over previous
#include <cuda_runtime.h>
#include <cstdint>
#include <math.h>

#define NNODES 87381
#define NLEAF  65536

// ---------------- scratch (device globals; no allocation anywhere) -----------
// gate order everywhere: [i | u | o | f], blocks of 160 cols
__device__ float g_E[87424u * 304];   // tf32-rounded embs, K padded 300->304
__device__ float g_X[87424u * 640];   // x-projections, stride 640
__device__ float g_H[87424u * 160];   // tf32-rounded h, stride 160 (pad cols 0)
__device__ float g_HS[16384 * 160];   // tf32-rounded child-sum of h
__device__ float g_C[NNODES * 150];   // cell states (exact fp32)
__device__ float g_P[16384 * 480];    // parent projections [i|u|o]
__device__ float g_F[65536u * 160];   // child f-projections
__device__ float g_Wx[304 * 640];     // [k][i|u|o|f], tf32-rounded, K pad 304
__device__ float g_Wh[160 * 640];     // [k][i|u|o|f], tf32-rounded, K pad 160
__device__ float g_bx[640];           // [i|u|o|f] exact
__device__ float g_bh[640];           // [i|u|o|f] exact

__device__ __forceinline__ float sigf(float x) { return 1.0f / (1.0f + expf(-x)); }

__device__ __forceinline__ float to_tf32(float x) {
    unsigned u;
    asm("cvt.rna.tf32.f32 %0, %1;" : "=r"(u) : "f"(x));
    return __uint_as_float(u);
}

__device__ __forceinline__ void mma8(float* d, const unsigned* a, const unsigned* b) {
    asm volatile(
        "mma.sync.aligned.m16n8k8.row.col.f32.tf32.tf32.f32 "
        "{%0,%1,%2,%3}, {%4,%5,%6,%7}, {%8,%9}, {%0,%1,%2,%3};\n"
        : "+f"(d[0]), "+f"(d[1]), "+f"(d[2]), "+f"(d[3])
        : "r"(a[0]), "r"(a[1]), "r"(a[2]), "r"(a[3]), "r"(b[0]), "r"(b[1]));
}

__device__ __forceinline__ void cp16(uint32_t dst, const void* src) {
    asm volatile("cp.async.ca.shared.global [%0], [%1], 16;" :: "r"(dst), "l"(src));
}
#define CP_COMMIT() asm volatile("cp.async.commit_group;" ::: "memory")
#define CP_WAIT(n)  asm volatile("cp.async.wait_group %0;" :: "n"(n) : "memory")

// ---------------- pre-round embs to tf32 (K padded) ---------------------------
__global__ void round_embs_kernel(const float* __restrict__ embs)
{
    int idx = blockIdx.x * blockDim.x + threadIdx.x;
    if (idx >= 87424 * 304) return;
    int r = idx / 304, c = idx - r * 304;
    float v = 0.0f;
    if (r < NNODES && c < 300) v = embs[r * 300 + c];
    g_E[idx] = to_tf32(v);
}

// ---------------- weight packing ----------------------------------------------
__global__ void pack_kernel(
    const float* Wix, const float* bix, const float* Wfx, const float* bfx,
    const float* Wux, const float* bux, const float* Wox, const float* box_,
    const float* Wih, const float* bih, const float* Wfh, const float* bfh,
    const float* Wuh, const float* buh, const float* Woh, const float* boh)
{
    const int T0 = 304 * 640;           // Wx
    const int T1 = T0 + 160 * 640;      // Wh
    const int T2 = T1 + 640;            // bx
    const int T3 = T2 + 640;            // bh
    for (int idx = blockIdx.x * blockDim.x + threadIdx.x; idx < T3;
         idx += gridDim.x * blockDim.x) {
        if (idx < T0) {
            int r = idx / 640, c = idx % 640, m = c / 160, cc = c % 160;
            float v = 0.0f;
            if (r < 300 && cc < 150) {
                const float* W = (m == 0) ? Wix : (m == 1) ? Wux : (m == 2) ? Wox : Wfx;
                v = W[r * 150 + cc];
            }
            g_Wx[idx] = to_tf32(v);
        } else if (idx < T1) {
            int t = idx - T0;
            int r = t / 640, c = t % 640, m = c / 160, cc = c % 160;
            float v = 0.0f;
            if (r < 150 && cc < 150) {
                const float* W = (m == 0) ? Wih : (m == 1) ? Wuh : (m == 2) ? Woh : Wfh;
                v = W[r * 150 + cc];
            }
            g_Wh[t] = to_tf32(v);
        } else if (idx < T2) {
            int c = idx - T1, m = c / 160, cc = c % 160;
            float v = 0.0f;
            if (cc < 150) {
                const float* b = (m == 0) ? bix : (m == 1) ? bux : (m == 2) ? box_ : bfx;
                v = b[cc];
            }
            g_bx[c] = v;
        } else {
            int c = idx - T2, m = c / 160, cc = c % 160;
            float v = 0.0f;
            if (cc < 150) {
                const float* b = (m == 0) ? bih : (m == 1) ? buh : (m == 2) ? boh : bfh;
                v = b[cc];
            }
            g_bh[c] = v;
        }
    }
}

// ---------------- tf32 tensor-core GEMM, cp.async double-buffered -------------
// C[m0:m0+128, colblk(+)] = A[M x lda] @ B[k][640] cols [col0+colblk : +160)
// BM=128, BN=160, BK=16. 256 threads = 8 warps (2 m x 4 n); warp tile 64x40.
// A pre-rounded tf32, K padded (no guards in hot loop).
template<bool BIAS>
__global__ __launch_bounds__(256, 2)
void gemm_tf32(const float* __restrict__ A, int lda, int M,
               const float* __restrict__ B, int col0,
               float* __restrict__ C, int ldc,
               const float* __restrict__ bias, int nchunk)
{
    __shared__ float As[2][128][20];
    __shared__ float Bs[2][16][168];

    const int tid    = threadIdx.x;
    const int lane   = tid & 31;
    const int wid    = tid >> 5;
    const int m_warp = (wid >> 2) * 64;
    const int n_warp = (wid & 3) * 40;
    const int m0     = blockIdx.x * 128;
    const int colblk = blockIdx.y * 160;   // C column offset
    const int bcol0  = col0 + colblk;      // B column offset

    float acc[4][5][4];
#pragma unroll
    for (int i = 0; i < 4; i++)
#pragma unroll
        for (int j = 0; j < 5; j++)
#pragma unroll
            for (int q = 0; q < 4; q++) acc[i][j][q] = 0.0f;

    auto issue = [&](int st, int k0) {
        // A: 128 rows x 4 x 16B
#pragma unroll
        for (int e = 0; e < 2; e++) {
            int id = tid + e * 256;
            int r = id >> 2, cs = id & 3;
            uint32_t dst = (uint32_t)__cvta_generic_to_shared(&As[st][r][cs * 4]);
            cp16(dst, A + (size_t)(m0 + r) * lda + k0 + cs * 4);
        }
        // B: 16 rows x 40 x 16B
#pragma unroll
        for (int e = 0; e < 3; e++) {
            int id = tid + e * 256;
            if (id < 640) {
                int r = id / 40, cs = id - r * 40;
                uint32_t dst = (uint32_t)__cvta_generic_to_shared(&Bs[st][r][cs * 4]);
                cp16(dst, B + (size_t)(k0 + r) * 640 + bcol0 + cs * 4);
            }
        }
        CP_COMMIT();
    };

    issue(0, 0);
    issue(1, 16);

    for (int ch = 0; ch < nchunk; ch++) {
        if (ch + 1 < nchunk) { CP_WAIT(1); } else { CP_WAIT(0); }
        __syncthreads();
        const int st = ch & 1;

#pragma unroll
        for (int ks = 0; ks < 2; ks++) {
            const int kk = ks * 8;
            unsigned a[4][4], b[5][2];
            const int rA = m_warp + (lane >> 2);
            const int cA = kk + (lane & 3);
#pragma unroll
            for (int i = 0; i < 4; i++) {
                a[i][0] = __float_as_uint(As[st][rA + 16 * i][cA]);
                a[i][1] = __float_as_uint(As[st][rA + 16 * i + 8][cA]);
                a[i][2] = __float_as_uint(As[st][rA + 16 * i][cA + 4]);
                a[i][3] = __float_as_uint(As[st][rA + 16 * i + 8][cA + 4]);
            }
            const int rB = kk + (lane & 3);
            const int cB = n_warp + (lane >> 2);
#pragma unroll
            for (int j = 0; j < 5; j++) {
                b[j][0] = __float_as_uint(Bs[st][rB][cB + 8 * j]);
                b[j][1] = __float_as_uint(Bs[st][rB + 4][cB + 8 * j]);
            }
#pragma unroll
            for (int i = 0; i < 4; i++)
#pragma unroll
                for (int j = 0; j < 5; j++) mma8(acc[i][j], a[i], b[j]);
        }
        __syncthreads();
        if (ch + 2 < nchunk) issue(st, (ch + 2) * 16);
    }

    // epilogue
    const int r0 = m0 + m_warp + (lane >> 2);
    const int cl = n_warp + (lane & 3) * 2;
#pragma unroll
    for (int i = 0; i < 4; i++) {
#pragma unroll
        for (int h = 0; h < 2; h++) {
            int r = r0 + 16 * i + 8 * h;
            if (r < M) {
                float* crow = C + (size_t)r * ldc + colblk;
#pragma unroll
                for (int j = 0; j < 5; j++) {
                    int c = cl + 8 * j;
                    float v0 = acc[i][j][2 * h], v1 = acc[i][j][2 * h + 1];
                    if (BIAS) {
                        v0 += bias[bcol0 + c];
                        v1 += bias[bcol0 + c + 1];
                    }
                    crow[c]     = v0;
                    crow[c + 1] = v1;
                }
            }
        }
    }
}

// ---------------- child-sum of h (tf32-rounded) --------------------------------
__global__ void hsum_kernel(int off_c, int n)
{
    int idx = blockIdx.x * blockDim.x + threadIdx.x;
    if (idx >= n * 160) return;
    int p = idx / 160, j = idx - p * 160;
    const float* hp = g_H + (size_t)(off_c + 4 * p) * 160;
    g_HS[idx] = to_tf32(hp[j] + hp[160 + j] + hp[320 + j] + hp[480 + j]);
}

// ---------------- leaves -------------------------------------------------------
__global__ void leaf_kernel(float* __restrict__ out)
{
    int idx = blockIdx.x * blockDim.x + threadIdx.x;
    if (idx >= NLEAF * 160) return;
    int p = idx / 160, j = idx - p * 160;
    if (j >= 150) { g_H[(size_t)p * 160 + j] = 0.0f; return; }
    const float* Xr = g_X + (size_t)p * 640;
    float ig = sigf(Xr[j] + g_bh[j]);
    float ug = tanhf(Xr[160 + j] + g_bh[160 + j]);
    float og = sigf(Xr[320 + j] + g_bh[320 + j]);
    float c = ig * ug;
    g_C[(size_t)p * 150 + j] = c;
    float h = og * tanhf(c);
    out[(size_t)p * 150 + j] = h;
    g_H[(size_t)p * 160 + j] = to_tf32(h);
}

// ---------------- internal level (GEMM path, d=1..3) ---------------------------
__global__ void level_kernel(float* __restrict__ out, int off_p, int off_c, int n)
{
    int idx = blockIdx.x * blockDim.x + threadIdx.x;
    if (idx >= n * 160) return;
    int p = idx / 160, j = idx - p * 160;
    int g = off_p + p;
    if (j >= 150) { g_H[(size_t)g * 160 + j] = 0.0f; return; }
    const float* Xr = g_X + (size_t)g * 640;
    const float* Pr = g_P + (size_t)p * 480;

    float ig = sigf(Xr[j]        + Pr[j]       + g_bh[j]);
    float ug = tanhf(Xr[160 + j] + Pr[160 + j] + g_bh[160 + j]);
    float og = sigf(Xr[320 + j]  + Pr[320 + j] + g_bh[320 + j]);
    float xf = Xr[480 + j] + g_bh[480 + j];

    float fc = 0.0f;
#pragma unroll
    for (int k = 0; k < 4; k++) {
        int cl = 4 * p + k;
        float f = sigf(xf + g_F[(size_t)cl * 160 + j]);
        fc = fmaf(f, g_C[(size_t)(off_c + cl) * 150 + j], fc);
    }
    float c = fmaf(ig, ug, fc);
    g_C[(size_t)g * 150 + j] = c;
    float h = og * tanhf(c);
    out[(size_t)g * 150 + j] = h;
    g_H[(size_t)g * 160 + j] = to_tf32(h);
}

// ---------------- fused small level (d=4..8, n<=256) ---------------------------
__global__ __launch_bounds__(160)
void small_level_kernel(float* __restrict__ out, int off_p, int off_c)
{
    int p = blockIdx.x, j = threadIdx.x;
    __shared__ float hs[160];
    __shared__ float hch[4][160];
    int g = off_p + p;
    float h0 = g_H[(size_t)(off_c + 4 * p + 0) * 160 + j];
    float h1 = g_H[(size_t)(off_c + 4 * p + 1) * 160 + j];
    float h2 = g_H[(size_t)(off_c + 4 * p + 2) * 160 + j];
    float h3 = g_H[(size_t)(off_c + 4 * p + 3) * 160 + j];
    hch[0][j] = h0; hch[1][j] = h1; hch[2][j] = h2; hch[3][j] = h3;
    hs[j] = h0 + h1 + h2 + h3;
    __syncthreads();

    float di = 0.f, du = 0.f, dog = 0.f;
    float df0 = 0.f, df1 = 0.f, df2 = 0.f, df3 = 0.f;
#pragma unroll 4
    for (int m = 0; m < 160; m++) {
        float hm = hs[m];
        const float* wrow = g_Wh + m * 640;
        di  = fmaf(hm, wrow[j], di);
        du  = fmaf(hm, wrow[160 + j], du);
        dog = fmaf(hm, wrow[320 + j], dog);
        float wf = wrow[480 + j];
        df0 = fmaf(hch[0][m], wf, df0);
        df1 = fmaf(hch[1][m], wf, df1);
        df2 = fmaf(hch[2][m], wf, df2);
        df3 = fmaf(hch[3][m], wf, df3);
    }
    if (j < 150) {
        const float* Xr = g_X + (size_t)g * 640;
        float ig = sigf(Xr[j] + di + g_bh[j]);
        float ug = tanhf(Xr[160 + j] + du + g_bh[160 + j]);
        float og = sigf(Xr[320 + j] + dog + g_bh[320 + j]);
        float xf = Xr[480 + j] + g_bh[480 + j];
        float fc = sigf(xf + df0) * g_C[(size_t)(off_c + 4 * p + 0) * 150 + j]
                 + sigf(xf + df1) * g_C[(size_t)(off_c + 4 * p + 1) * 150 + j]
                 + sigf(xf + df2) * g_C[(size_t)(off_c + 4 * p + 2) * 150 + j]
                 + sigf(xf + df3) * g_C[(size_t)(off_c + 4 * p + 3) * 150 + j];
        float c = fmaf(ig, ug, fc);
        g_C[(size_t)g * 150 + j] = c;
        float h = og * tanhf(c);
        out[(size_t)g * 150 + j] = h;
        g_H[(size_t)g * 160 + j] = to_tf32(h);
    } else {
        g_H[(size_t)g * 160 + j] = 0.0f;
    }
}

// ---------------- host orchestration -------------------------------------------
extern "C" void kernel_launch(void* const* d_in, const int* in_sizes, int n_in,
                              void* d_out, int out_size)
{
    const float* embs = (const float*)d_in[0];
    const float* Wix = (const float*)d_in[1];  const float* bix = (const float*)d_in[2];
    const float* Wfx = (const float*)d_in[3];  const float* bfx = (const float*)d_in[4];
    const float* Wux = (const float*)d_in[5];  const float* bux = (const float*)d_in[6];
    const float* Wox = (const float*)d_in[7];  const float* box_ = (const float*)d_in[8];
    const float* Wih = (const float*)d_in[9];  const float* bih = (const float*)d_in[10];
    const float* Wfh = (const float*)d_in[11]; const float* bfh = (const float*)d_in[12];
    const float* Wuh = (const float*)d_in[13]; const float* buh = (const float*)d_in[14];
    const float* Woh = (const float*)d_in[15]; const float* boh = (const float*)d_in[16];
    float* out = (float*)d_out;

    float *pE, *pX, *pH, *pHS, *pWx, *pWh, *pbx, *pP, *pF;
    cudaGetSymbolAddress((void**)&pE,  g_E);
    cudaGetSymbolAddress((void**)&pX,  g_X);
    cudaGetSymbolAddress((void**)&pH,  g_H);
    cudaGetSymbolAddress((void**)&pHS, g_HS);
    cudaGetSymbolAddress((void**)&pWx, g_Wx);
    cudaGetSymbolAddress((void**)&pWh, g_Wh);
    cudaGetSymbolAddress((void**)&pbx, g_bx);
    cudaGetSymbolAddress((void**)&pP,  g_P);
    cudaGetSymbolAddress((void**)&pF,  g_F);

    static const int SIZES[9] = {65536, 16384, 4096, 1024, 256, 64, 16, 4, 1};
    static const int OFF[9]   = {0, 65536, 81920, 86016, 87040, 87296, 87360, 87376, 87380};

    // 1. pre-round embs, pack weights
    round_embs_kernel<<<(87424 * 304 + 255) / 256, 256>>>(embs);
    pack_kernel<<<512, 256>>>(Wix, bix, Wfx, bfx, Wux, bux, Wox, box_,
                              Wih, bih, Wfh, bfh, Wuh, buh, Woh, boh);

    // 2. X projections (tf32 mma + cp.async)
    //    leaves need only [i|u|o] (cols 0..479); internal nodes need all 640.
    {
        dim3 grid(65536 / 128, 3);
        gemm_tf32<true><<<grid, 256>>>(pE, 304, 65536, pWx, 0, pX, 640, pbx, 19);
    }
    {
        dim3 grid((21845 + 127) / 128, 4);
        gemm_tf32<true><<<grid, 256>>>(pE + (size_t)65536 * 304, 304, 21845, pWx, 0,
                                       pX + (size_t)65536 * 640, 640, pbx, 19);
    }

    // 3. leaves
    leaf_kernel<<<(NLEAF * 160 + 255) / 256, 256>>>(out);

    // 4. levels 1..3: GEMM path
    for (int d = 1; d <= 3; d++) {
        int n  = SIZES[d];
        int np = SIZES[d - 1];
        hsum_kernel<<<(n * 160 + 255) / 256, 256>>>(OFF[d - 1], n);
        {   // P = h_sum @ [W_ih|W_uh|W_oh]
            dim3 grid(n / 128, 3);
            gemm_tf32<false><<<grid, 256>>>(pHS, 160, n, pWh, 0, pP, 480, nullptr, 10);
        }
        {   // F = h_children @ W_fh  (B cols 480..639)
            dim3 grid(np / 128, 1);
            gemm_tf32<false><<<grid, 256>>>(pH + (size_t)OFF[d - 1] * 160, 160, np,
                                            pWh, 480, pF, 160, nullptr, 10);
        }
        level_kernel<<<(n * 160 + 255) / 256, 256>>>(out, OFF[d], OFF[d - 1], n);
    }

    // 5. levels 4..8: fused fp32 kernels (n = 256, 64, 16, 4, 1)
    for (int d = 4; d <= 8; d++)
        small_level_kernel<<<SIZES[d], 160>>>(out, OFF[d], OFF[d - 1]);
}

// round 5
// speedup vs baseline: 5.2498x; 1.2526x over previous
#include <cuda_runtime.h>
#include <cstdint>
#include <math.h>

#define NNODES 87381
#define NLEAF  65536

// =================== scratch (device globals; no allocation) =================
// Tiled-interleaved layout for all GEMM A operands (128-row x 16-col chunks):
//   float index(row,k) = (rowblk*NCH + chunk)*2048 + ((s*128+m)*4 + c4)*2 + half
//   where chunk=k>>4, kk=k&15, s=kk>>3, c4=kk&3, half=(kk&7)>>2, m=row&127.
// This makes every mma fragment a conflict-free LDS.64 (pair k, k+4).
__device__ float g_E2[683u * 19 * 2048];   // tf32-rounded embs, tiled (rows pad 87424)
__device__ float g_X [87424u * 640];       // x-projections [i|u|o|f], stride 640
__device__ float g_H2[683u * 10 * 2048];   // tf32-rounded h, tiled, 160-padded
__device__ float g_HS2[128u * 10 * 2048];  // tf32-rounded child-sum, tiled (16384 rows)
__device__ float g_C [NNODES * 150];       // cell states (exact fp32)
__device__ float g_P [16384u * 480];       // parent projections [i|u|o]
__device__ float g_F [65536u * 160];       // child f-projections
// B operands, fragment-row layout: [chunk][s][c4][col(640)][half]  (rows of 1280 floats)
__device__ float g_Wxp[19 * 10240];        // Wx packed, tf32-rounded, K pad 304
__device__ float g_Whp[10 * 10240];        // Wh packed, tf32-rounded, K pad 160
__device__ float g_Wh2[160 * 640];         // Wh plain [k][i|u|o|f] for fused small levels
__device__ float g_bx[640];
__device__ float g_bh[640];

// =================== helpers ==================================================
__device__ __forceinline__ float to_tf32(float x) {
    unsigned u;
    asm("cvt.rna.tf32.f32 %0, %1;" : "=r"(u) : "f"(x));
    return __uint_as_float(u);
}
__device__ __forceinline__ float sigf(float x) {
    return __fdividef(1.0f, 1.0f + __expf(-x));
}
__device__ __forceinline__ float tanh_fast(float x) {
    return __fdividef(2.0f, 1.0f + __expf(-2.0f * x)) - 1.0f;
}
// scalar float position of h(row, j) in tiled H buffer (NCH = 10)
__device__ __forceinline__ size_t hpos(int row, int j) {
    int rb = row >> 7, m = row & 127;
    int chunk = j >> 4, kk = j & 15;
    int s = kk >> 3, r = kk & 7;
    return ((size_t)(rb * 10 + chunk) << 11) + (size_t)((((s << 7) + m) * 4 + (r & 3)) * 2 + (r >> 2));
}
__device__ __forceinline__ void mma8(float* d, const unsigned* a, const unsigned* b) {
    asm volatile(
        "mma.sync.aligned.m16n8k8.row.col.f32.tf32.tf32.f32 "
        "{%0,%1,%2,%3}, {%4,%5,%6,%7}, {%8,%9}, {%0,%1,%2,%3};\n"
        : "+f"(d[0]), "+f"(d[1]), "+f"(d[2]), "+f"(d[3])
        : "r"(a[0]), "r"(a[1]), "r"(a[2]), "r"(a[3]), "r"(b[0]), "r"(b[1]));
}
__device__ __forceinline__ void cp16(uint32_t dst, const void* src) {
    asm volatile("cp.async.ca.shared.global [%0], [%1], 16;" :: "r"(dst), "l"(src));
}
#define CP_COMMIT() asm volatile("cp.async.commit_group;" ::: "memory")
#define CP_WAIT2()  asm volatile("cp.async.wait_group 2;" ::: "memory")

// =================== embs -> tiled tf32 ======================================
__global__ void round_embs_kernel(const float* __restrict__ embs)
{
    int o2 = blockIdx.x * blockDim.x + threadIdx.x;     // float2 index
    const int TOT = 683 * 19 * 1024;
    if (o2 >= TOT) return;
    int w2 = o2 & 1023, t = o2 >> 10;
    int chunk = t % 19, rb = t / 19;
    int c4 = w2 & 3, m = (w2 >> 2) & 127, s = w2 >> 9;
    int row = (rb << 7) + m;
    int k = chunk * 16 + s * 8 + c4;                    // pair (k, k+4)
    float2 v = make_float2(0.f, 0.f);
    if (row < NNODES) {
        const float* er = embs + (size_t)row * 300;
        if (k < 300)     v.x = er[k];
        if (k + 4 < 300) v.y = er[k + 4];
    }
    v.x = to_tf32(v.x);
    v.y = to_tf32(v.y);
    ((float2*)g_E2)[o2] = v;
}

// =================== weight packing ==========================================
__global__ void pack_kernel(
    const float* Wix, const float* bix, const float* Wfx, const float* bfx,
    const float* Wux, const float* bux, const float* Wox, const float* box_,
    const float* Wih, const float* bih, const float* Wfh, const float* bfh,
    const float* Wuh, const float* buh, const float* Woh, const float* boh)
{
    const int T0 = 19 * 10240;          // Wxp
    const int T1 = T0 + 10 * 10240;     // Whp
    const int T2 = T1 + 160 * 640;      // Wh2
    const int T3 = T2 + 640;            // bx
    const int T4 = T3 + 640;            // bh
    for (int idx = blockIdx.x * blockDim.x + threadIdx.x; idx < T4;
         idx += gridDim.x * blockDim.x) {
        if (idx < T0) {
            int rowI = idx / 1280, w = idx % 1280;
            int col = w >> 1, half = w & 1;
            int chunk = rowI >> 3, rr = rowI & 7;
            int k = chunk * 16 + (rr >> 2) * 8 + half * 4 + (rr & 3);
            int m = col / 160, cc = col % 160;
            float v = 0.f;
            if (k < 300 && cc < 150) {
                const float* W = (m == 0) ? Wix : (m == 1) ? Wux : (m == 2) ? Wox : Wfx;
                v = W[k * 150 + cc];
            }
            g_Wxp[idx] = to_tf32(v);
        } else if (idx < T1) {
            int t = idx - T0;
            int rowI = t / 1280, w = t % 1280;
            int col = w >> 1, half = w & 1;
            int chunk = rowI >> 3, rr = rowI & 7;
            int k = chunk * 16 + (rr >> 2) * 8 + half * 4 + (rr & 3);
            int m = col / 160, cc = col % 160;
            float v = 0.f;
            if (k < 150 && cc < 150) {
                const float* W = (m == 0) ? Wih : (m == 1) ? Wuh : (m == 2) ? Woh : Wfh;
                v = W[k * 150 + cc];
            }
            g_Whp[t] = to_tf32(v);
        } else if (idx < T2) {
            int t = idx - T1;
            int k = t / 640, c = t % 640, m = c / 160, cc = c % 160;
            float v = 0.f;
            if (k < 150 && cc < 150) {
                const float* W = (m == 0) ? Wih : (m == 1) ? Wuh : (m == 2) ? Woh : Wfh;
                v = W[k * 150 + cc];
            }
            g_Wh2[t] = v;
        } else if (idx < T3) {
            int c = idx - T2, m = c / 160, cc = c % 160;
            float v = 0.f;
            if (cc < 150) {
                const float* b = (m == 0) ? bix : (m == 1) ? bux : (m == 2) ? box_ : bfx;
                v = b[cc];
            }
            g_bx[c] = v;
        } else {
            int c = idx - T3, m = c / 160, cc = c % 160;
            float v = 0.f;
            if (cc < 150) {
                const float* b = (m == 0) ? bih : (m == 1) ? buh : (m == 2) ? boh : bfh;
                v = b[cc];
            }
            g_bh[c] = v;
        }
    }
}

// =================== tf32 mma GEMM, 3-stage cp.async =========================
// C[blk.x*128 : +128, blk.y*160 : +160] = A @ B(cols col0+colblk..+160) (+bias)
// A: tiled-interleaved (nch chunks). B: g_W*p fragment-row layout.
// 256 thr = 8 warps (2m x 4n), warp tile 64x40. All LDS are conflict-free .64.
// Stage = 4672 floats: A 2048 + B 8 rows x 164 float2 (pad 164 -> bank shift 8).
template<bool BIAS>
__global__ __launch_bounds__(256, 2)
void gemm_tf32(const float* __restrict__ A2, int nch,
               const float* __restrict__ Bp, int col0,
               float* __restrict__ C, int ldc,
               const float* __restrict__ bias, int nchunk)
{
    extern __shared__ __align__(16) float sm[];
    const uint32_t sbase = (uint32_t)__cvta_generic_to_shared(sm);

    const int tid    = threadIdx.x;
    const int lane   = tid & 31;
    const int wid    = tid >> 5;
    const int m_warp = (wid >> 2) * 64;
    const int n_warp = (wid & 3) * 40;
    const int m0     = blockIdx.x * 128;
    const int colblk = blockIdx.y * 160;
    const int bcol0  = col0 + colblk;
    const int c4     = lane & 3;
    const int q      = lane >> 2;

    float acc[4][5][4];
#pragma unroll
    for (int i = 0; i < 4; i++)
#pragma unroll
        for (int j = 0; j < 5; j++)
#pragma unroll
            for (int p = 0; p < 4; p++) acc[i][j][p] = 0.0f;

    auto issue = [&](int st, int ch) {
        if (ch < nchunk) {
            const float* At = A2 + ((size_t)blockIdx.x * nch + ch) * 2048;
            uint32_t da = sbase + st * 18688 + tid * 16;
            cp16(da, At + tid * 4);
            cp16(da + 4096, At + tid * 4 + 1024);
            const float* Bt = Bp + (size_t)ch * 10240 + (size_t)bcol0 * 2;
#pragma unroll
            for (int e = 0; e < 3; e++) {
                int id = tid + e * 256;
                if (id < 640) {
                    int r = id / 80, o = id - r * 80;
                    cp16(sbase + st * 18688 + 8192 + r * 1312 + o * 16,
                         Bt + r * 1280 + o * 4);
                }
            }
        }
        CP_COMMIT();
    };

    issue(0, 0);
    issue(1, 1);
    issue(2, 2);

    int st = 0;
    for (int ch = 0; ch < nchunk; ch++) {
        CP_WAIT2();
        __syncthreads();
        const float* stf = sm + st * 4672;
        const float2* Af = (const float2*)stf;
        const float2* Bf = (const float2*)(stf + 2048);

#pragma unroll
        for (int s = 0; s < 2; s++) {
            unsigned a[4][4];
#pragma unroll
            for (int i = 0; i < 4; i++) {
                int m1 = m_warp + 16 * i + q;
                float2 lo = Af[(s * 128 + m1) * 4 + c4];
                float2 hi = Af[(s * 128 + m1 + 8) * 4 + c4];
                a[i][0] = __float_as_uint(lo.x);
                a[i][1] = __float_as_uint(hi.x);
                a[i][2] = __float_as_uint(lo.y);
                a[i][3] = __float_as_uint(hi.y);
            }
            unsigned b[5][2];
#pragma unroll
            for (int j = 0; j < 5; j++) {
                float2 bv = Bf[(s * 4 + c4) * 164 + n_warp + q + 8 * j];
                b[j][0] = __float_as_uint(bv.x);
                b[j][1] = __float_as_uint(bv.y);
            }
#pragma unroll
            for (int i = 0; i < 4; i++)
#pragma unroll
                for (int j = 0; j < 5; j++) mma8(acc[i][j], a[i], b[j]);
        }
        __syncthreads();
        issue(st, ch + 3);
        st = (st == 2) ? 0 : st + 1;
    }

    // epilogue (all C buffers padded to 128-row multiples: unguarded)
    const int r0 = m0 + m_warp + q;
    const int cl = n_warp + c4 * 2;
#pragma unroll
    for (int i = 0; i < 4; i++) {
#pragma unroll
        for (int h = 0; h < 2; h++) {
            int r = r0 + 16 * i + 8 * h;
            float* crow = C + (size_t)r * ldc + colblk;
#pragma unroll
            for (int j = 0; j < 5; j++) {
                int c = cl + 8 * j;
                float2 v = make_float2(acc[i][j][2 * h], acc[i][j][2 * h + 1]);
                if (BIAS) {
                    v.x += bias[bcol0 + c];
                    v.y += bias[bcol0 + c + 1];
                }
                *(float2*)(crow + c) = v;
            }
        }
    }
}

// =================== child-sum of h (tiled -> tiled, tf32) ====================
__global__ void hsum_kernel(int off_c, int n)
{
    int o2 = blockIdx.x * blockDim.x + threadIdx.x;     // float2 index into HS2
    const int TOT = (n >> 7) * 10 * 1024;
    if (o2 >= TOT) return;
    int w2 = o2 & 1023, t = o2 >> 10;
    int chunk = t % 10, rb = t / 10;
    int c4 = w2 & 3, m = (w2 >> 2) & 127, s = w2 >> 9;
    int p = (rb << 7) + m;
    const float2* H2 = (const float2*)g_H2;
    float2 a = make_float2(0.f, 0.f);
#pragma unroll
    for (int k = 0; k < 4; k++) {
        int crow = off_c + 4 * p + k;
        float2 hv = H2[((size_t)((crow >> 7) * 10 + chunk) << 10) +
                       (size_t)(((s << 7) + (crow & 127)) * 4 + c4)];
        a.x += hv.x;
        a.y += hv.y;
    }
    a.x = to_tf32(a.x);
    a.y = to_tf32(a.y);
    ((float2*)g_HS2)[o2] = a;
}

// =================== leaves ====================================================
__global__ void leaf_kernel(float* __restrict__ out)
{
    int idx = blockIdx.x * blockDim.x + threadIdx.x;
    if (idx >= NLEAF * 160) return;
    int p = idx / 160, j = idx - p * 160;
    if (j >= 150) { g_H2[hpos(p, j)] = 0.0f; return; }
    const float* Xr = g_X + (size_t)p * 640;
    float ig = sigf(Xr[j] + g_bh[j]);
    float ug = tanh_fast(Xr[160 + j] + g_bh[160 + j]);
    float og = sigf(Xr[320 + j] + g_bh[320 + j]);
    float c = ig * ug;
    g_C[(size_t)p * 150 + j] = c;
    float h = og * tanh_fast(c);
    out[(size_t)p * 150 + j] = h;
    g_H2[hpos(p, j)] = to_tf32(h);
}

// =================== internal level (GEMM path, d=1..3) ========================
__global__ void level_kernel(float* __restrict__ out, int off_p, int off_c, int n)
{
    int idx = blockIdx.x * blockDim.x + threadIdx.x;
    if (idx >= n * 160) return;
    int p = idx / 160, j = idx - p * 160;
    int g = off_p + p;
    if (j >= 150) { g_H2[hpos(g, j)] = 0.0f; return; }
    const float* Xr = g_X + (size_t)g * 640;
    const float* Pr = g_P + (size_t)p * 480;

    float ig = sigf(Xr[j]        + Pr[j]       + g_bh[j]);
    float ug = tanh_fast(Xr[160 + j] + Pr[160 + j] + g_bh[160 + j]);
    float og = sigf(Xr[320 + j]  + Pr[320 + j] + g_bh[320 + j]);
    float xf = Xr[480 + j] + g_bh[480 + j];

    float fc = 0.0f;
#pragma unroll
    for (int k = 0; k < 4; k++) {
        int cl = 4 * p + k;
        float f = sigf(xf + g_F[(size_t)cl * 160 + j]);
        fc = fmaf(f, g_C[(size_t)(off_c + cl) * 150 + j], fc);
    }
    float c = fmaf(ig, ug, fc);
    g_C[(size_t)g * 150 + j] = c;
    float h = og * tanh_fast(c);
    out[(size_t)g * 150 + j] = h;
    g_H2[hpos(g, j)] = to_tf32(h);
}

// =================== fused small level (d=4..8, n<=256) ========================
__global__ __launch_bounds__(160)
void small_level_kernel(float* __restrict__ out, int off_p, int off_c)
{
    int p = blockIdx.x, j = threadIdx.x;
    __shared__ float hs[160];
    __shared__ float hch[4][160];
    int g = off_p + p;
    float h0 = g_H2[hpos(off_c + 4 * p + 0, j)];
    float h1 = g_H2[hpos(off_c + 4 * p + 1, j)];
    float h2 = g_H2[hpos(off_c + 4 * p + 2, j)];
    float h3 = g_H2[hpos(off_c + 4 * p + 3, j)];
    hch[0][j] = h0; hch[1][j] = h1; hch[2][j] = h2; hch[3][j] = h3;
    hs[j] = h0 + h1 + h2 + h3;
    __syncthreads();

    float di = 0.f, du = 0.f, dog = 0.f;
    float df0 = 0.f, df1 = 0.f, df2 = 0.f, df3 = 0.f;
#pragma unroll 4
    for (int m = 0; m < 160; m++) {
        float hm = hs[m];
        const float* wrow = g_Wh2 + m * 640;
        di  = fmaf(hm, wrow[j], di);
        du  = fmaf(hm, wrow[160 + j], du);
        dog = fmaf(hm, wrow[320 + j], dog);
        float wf = wrow[480 + j];
        df0 = fmaf(hch[0][m], wf, df0);
        df1 = fmaf(hch[1][m], wf, df1);
        df2 = fmaf(hch[2][m], wf, df2);
        df3 = fmaf(hch[3][m], wf, df3);
    }
    if (j < 150) {
        const float* Xr = g_X + (size_t)g * 640;
        float ig = sigf(Xr[j] + di + g_bh[j]);
        float ug = tanh_fast(Xr[160 + j] + du + g_bh[160 + j]);
        float og = sigf(Xr[320 + j] + dog + g_bh[320 + j]);
        float xf = Xr[480 + j] + g_bh[480 + j];
        float fc = sigf(xf + df0) * g_C[(size_t)(off_c + 4 * p + 0) * 150 + j]
                 + sigf(xf + df1) * g_C[(size_t)(off_c + 4 * p + 1) * 150 + j]
                 + sigf(xf + df2) * g_C[(size_t)(off_c + 4 * p + 2) * 150 + j]
                 + sigf(xf + df3) * g_C[(size_t)(off_c + 4 * p + 3) * 150 + j];
        float c = fmaf(ig, ug, fc);
        g_C[(size_t)g * 150 + j] = c;
        float h = og * tanh_fast(c);
        out[(size_t)g * 150 + j] = h;
        g_H2[hpos(g, j)] = to_tf32(h);
    } else {
        g_H2[hpos(g, j)] = 0.0f;
    }
}

// =================== host orchestration ========================================
extern "C" void kernel_launch(void* const* d_in, const int* in_sizes, int n_in,
                              void* d_out, int out_size)
{
    const float* embs = (const float*)d_in[0];
    const float* Wix = (const float*)d_in[1];  const float* bix = (const float*)d_in[2];
    const float* Wfx = (const float*)d_in[3];  const float* bfx = (const float*)d_in[4];
    const float* Wux = (const float*)d_in[5];  const float* bux = (const float*)d_in[6];
    const float* Wox = (const float*)d_in[7];  const float* box_ = (const float*)d_in[8];
    const float* Wih = (const float*)d_in[9];  const float* bih = (const float*)d_in[10];
    const float* Wfh = (const float*)d_in[11]; const float* bfh = (const float*)d_in[12];
    const float* Wuh = (const float*)d_in[13]; const float* buh = (const float*)d_in[14];
    const float* Woh = (const float*)d_in[15]; const float* boh = (const float*)d_in[16];
    float* out = (float*)d_out;

    float *pE2, *pX, *pH2, *pHS2, *pWxp, *pWhp, *pbx, *pP, *pF;
    cudaGetSymbolAddress((void**)&pE2,  g_E2);
    cudaGetSymbolAddress((void**)&pX,   g_X);
    cudaGetSymbolAddress((void**)&pH2,  g_H2);
    cudaGetSymbolAddress((void**)&pHS2, g_HS2);
    cudaGetSymbolAddress((void**)&pWxp, g_Wxp);
    cudaGetSymbolAddress((void**)&pWhp, g_Whp);
    cudaGetSymbolAddress((void**)&pbx,  g_bx);
    cudaGetSymbolAddress((void**)&pP,   g_P);
    cudaGetSymbolAddress((void**)&pF,   g_F);

    static const int SIZES[9] = {65536, 16384, 4096, 1024, 256, 64, 16, 4, 1};
    static const int OFF[9]   = {0, 65536, 81920, 86016, 87040, 87296, 87360, 87376, 87380};
    const int SMEM = 3 * 4672 * 4;  // 56064 B

    cudaFuncSetAttribute(gemm_tf32<true>,
                         cudaFuncAttributeMaxDynamicSharedMemorySize, SMEM);
    cudaFuncSetAttribute(gemm_tf32<false>,
                         cudaFuncAttributeMaxDynamicSharedMemorySize, SMEM);

    // 1. pre-round + tile embs; pack weights
    round_embs_kernel<<<(683 * 19 * 1024 + 255) / 256, 256>>>(embs);
    pack_kernel<<<512, 256>>>(Wix, bix, Wfx, bfx, Wux, bux, Wox, box_,
                              Wih, bih, Wfh, bfh, Wuh, buh, Woh, boh);

    // 2. X projections: leaves need [i|u|o] only, internal nodes all 4 gates
    {
        dim3 grid(512, 3);
        gemm_tf32<true><<<grid, 256, SMEM>>>(pE2, 19, pWxp, 0, pX, 640, pbx, 19);
    }
    {
        dim3 grid(171, 4);
        gemm_tf32<true><<<grid, 256, SMEM>>>(pE2 + (size_t)512 * 19 * 2048, 19, pWxp, 0,
                                             pX + (size_t)65536 * 640, 640, pbx, 19);
    }

    // 3. leaves
    leaf_kernel<<<(NLEAF * 160 + 255) / 256, 256>>>(out);

    // 4. levels 1..3: GEMM path
    for (int d = 1; d <= 3; d++) {
        int n  = SIZES[d];
        int np = SIZES[d - 1];
        hsum_kernel<<<((n >> 7) * 10 * 1024 + 255) / 256, 256>>>(OFF[d - 1], n);
        {   // P = h_sum @ [W_ih|W_uh|W_oh]
            dim3 grid(n / 128, 3);
            gemm_tf32<false><<<grid, 256, SMEM>>>(pHS2, 10, pWhp, 0, pP, 480, nullptr, 10);
        }
        {   // F = h_children @ W_fh  (B cols 480..639)
            dim3 grid(np / 128, 1);
            gemm_tf32<false><<<grid, 256, SMEM>>>(pH2 + (size_t)OFF[d - 1] * 160, 10,
                                                  pWhp, 480, pF, 160, nullptr, 10);
        }
        level_kernel<<<(n * 160 + 255) / 256, 256>>>(out, OFF[d], OFF[d - 1], n);
    }

    // 5. levels 4..8: fused fp32 kernels (n = 256, 64, 16, 4, 1)
    for (int d = 4; d <= 8; d++)
        small_level_kernel<<<SIZES[d], 160>>>(out, OFF[d], OFF[d - 1]);
}